// round 1
// baseline (speedup 1.0000x reference)
#include <cuda_runtime.h>
#include <cstdint>

// Haar DWT level-1 on x: (8, 64, 512, 512) fp32 -> 4 quadrants (8,64,256,256)
// concatenated in d_out as [ll | lh | hl | hh].
//
// Per thread: one 2x4 input patch (two float4 loads from adjacent rows)
// -> two 2x2 Haar butterflies -> one float2 store per quadrant.
//
// Dimensions (all powers of two):
//   planes P = 8*64 = 512, H = W = 512, outH = outW = 256
//   pair-of-output-cols per row: 256/2 = 128  (== one float4 of input per thread)
//   total threads = 512 * 256 * 128 = 16,777,216

__global__ __launch_bounds__(256, 8)
void haar_dwt_kernel(const float* __restrict__ in, float* __restrict__ out) {
    const unsigned idx = blockIdx.x * 256u + threadIdx.x;   // < 16,777,216
    const unsigned tx = idx & 127u;            // float4 index within input row (0..127)
    const unsigned oy = (idx >> 7) & 255u;     // output row (0..255)
    const unsigned p  = idx >> 15;             // plane (0..511)

    // Input: row pair 2*oy, 2*oy+1 of plane p; one float4 (4 consecutive cols).
    const float4* __restrict__ in4 =
        reinterpret_cast<const float4*>(in) + ((size_t)p * 512u + 2u * oy) * 128u + tx;
    const float4 r0 = in4[0];      // row 2*oy,   cols 4tx..4tx+3
    const float4 r1 = in4[128];    // row 2*oy+1, same cols (+512 floats)

    // Block 0: cols (4tx, 4tx+1) ; Block 1: cols (4tx+2, 4tx+3)
    // a = top-left, b = top-right, c = bot-left, d = bot-right
    const float a0 = r0.x, b0 = r0.y, c0 = r1.x, d0 = r1.y;
    const float a1 = r0.z, b1 = r0.w, c1 = r1.z, d1 = r1.w;

    const float ll0 = ( a0 + b0 + c0 + d0) * 0.5f;
    const float lh0 = (-a0 - b0 + c0 + d0) * 0.5f;
    const float hl0 = (-a0 + b0 - c0 + d0) * 0.5f;
    const float hh0 = ( a0 - b0 - c0 + d0) * 0.5f;

    const float ll1 = ( a1 + b1 + c1 + d1) * 0.5f;
    const float lh1 = (-a1 - b1 + c1 + d1) * 0.5f;
    const float hl1 = (-a1 + b1 - c1 + d1) * 0.5f;
    const float hh1 = ( a1 - b1 - c1 + d1) * 0.5f;

    // Output: element offset within a quadrant; obase is even -> float2 aligned.
    const size_t qsize = (size_t)512u * 256u * 256u;               // 33,554,432
    const size_t obase = (((size_t)p * 256u + oy) * 256u) + 2u * tx;

    *reinterpret_cast<float2*>(out + 0 * qsize + obase) = make_float2(ll0, ll1);
    *reinterpret_cast<float2*>(out + 1 * qsize + obase) = make_float2(lh0, lh1);
    *reinterpret_cast<float2*>(out + 2 * qsize + obase) = make_float2(hl0, hl1);
    *reinterpret_cast<float2*>(out + 3 * qsize + obase) = make_float2(hh0, hh1);
}

extern "C" void kernel_launch(void* const* d_in, const int* in_sizes, int n_in,
                              void* d_out, int out_size) {
    const float* x = (const float*)d_in[0];
    float* out = (float*)d_out;
    // 16,777,216 threads total
    haar_dwt_kernel<<<65536, 256>>>(x, out);
}